// round 10
// baseline (speedup 1.0000x reference)
#include <cuda_runtime.h>
#include <cstdint>
#include <math.h>

#define BATCH 4096
#define INF   128
#define OUTF  128
#define POST_STRIDE (OUTF * INF)      // 16384 floats per batch row of postacts
#define Y_ELEMS (BATCH * OUTF)        // 524288

// x_red stored TILE-TRANSPOSED for kan's access pattern:
// g_xredT4[i4][b] = float4( x_red[b][4*i4 .. 4*i4+3] ).  2 MB static scratch.
__device__ float4 g_xredT4[INF / 4][BATCH];

// ---------------------------------------------------------------------------
// Kernel 1: x_red[b, j] = sum_i x[b, i] * mask[j, i], written transposed.
// 128 blocks x 256 threads; 32 b-rows per block (two 16-row halves, one per
// thread half; both halves read the same mask lines -> L1 hits).
// ---------------------------------------------------------------------------
__global__ __launch_bounds__(256) void xred_kernel(const float* __restrict__ x,
                                                   const float* __restrict__ mask) {
    __shared__ float4 sx4[32][32];         // 32 b-rows x 128 floats

    const int tid = threadIdx.x;
    const int b0  = blockIdx.x * 32;
    const int j   = tid & 127;
    const int bh  = (tid >> 7) * 16;       // which 16-row half

    const float4* x4 = reinterpret_cast<const float4*>(x) + (size_t)b0 * 32;
#pragma unroll
    for (int k = 0; k < 4; ++k) {
        int idx = tid + k * 256;           // 0..1023
        sx4[idx >> 5][idx & 31] = x4[idx];
    }
    __syncthreads();

    const float4* m4 = reinterpret_cast<const float4*>(mask) + (size_t)j * 32;

    float acc[16];
#pragma unroll
    for (int b = 0; b < 16; ++b) acc[b] = 0.0f;

#pragma unroll 4
    for (int q = 0; q < 32; ++q) {
        float4 mv = __ldg(&m4[q]);
#pragma unroll
        for (int b = 0; b < 16; ++b) {
            float4 xv = sx4[bh + b][q];    // broadcast within warp: conflict-free
            acc[b] += mv.x * xv.x + mv.y * xv.y + mv.z * xv.z + mv.w * xv.w;
        }
    }

    const int i4   = j >> 2;
    const int comp = j & 3;
#pragma unroll
    for (int b = 0; b < 16; ++b)
        reinterpret_cast<float*>(&g_xredT4[i4][b0 + bh + b])[comp] = acc[b];
}

// ---------------------------------------------------------------------------
// Activation body. `id` is warp-uniform at every call site -> single branch
// taken per warp. MUFU fast paths (abs err ~1e-6), atanf stays libm.
// ---------------------------------------------------------------------------
__device__ __forceinline__ float apply_fn(int id, float z) {
    switch (id) {
        case 0: return z;
        case 1: return z * z;
        case 2: return z * z * z;
        case 3: return __sinf(z);
        case 4: {                                   // tanh, saturates at +/-inf
            float e = __expf(2.0f * z);
            return 1.0f - 2.0f * __fdividef(1.0f, e + 1.0f);
        }
        case 5: return __fdividef(1.0f, 1.0f + __expf(-z));   // sigmoid
        case 6: return __expf(-z * z);
        case 7: return fabsf(z);
        case 8: return atanf(z);
        default: return __expf(z);                  // id == 9
    }
}

// ---------------------------------------------------------------------------
// Kernel 2: main KAN layer, PIPELINED over 8 b-tiles per block.
// Grid: (r = 128, chunk = 16); each block owns 8 consecutive 32-batch tiles
// at fixed r. Double-buffered so[2]: tile t's bulk copy (cp.async.bulk,
// smem->gmem, one 512B row per thread of warp 0) overlaps tile t+1's compute.
// wait_group 1 keeps at most one copy in flight; drain exposed once per block.
// Lanes map to batch -> fun_id warp-uniform (no divergence). All smem traffic
// 128-bit; so rows stride-132 (conflict-free STS).
// ---------------------------------------------------------------------------
__global__ __launch_bounds__(256) void kan_kernel(const float4* __restrict__ affine4,
                                                  const int*   __restrict__ fids,
                                                  float*       __restrict__ out) {
    const int r       = blockIdx.x;
    const int b0_base = blockIdx.y << 8;   // 8 tiles * 32 batch

    __shared__ __align__(16) float so[2][32][132];
    __shared__ float4 saf[128];            // affine[r][i][0..3]
    __shared__ int4   sf4[32];             // fun_ids packed 4-wide
    __shared__ float  spart[8][32];

    const int tid = threadIdx.x;

    if (tid < 128) {
        saf[tid] = affine4[r * 128 + tid];
    } else if (tid < 160) {
        sf4[tid - 128] = reinterpret_cast<const int4*>(fids)[r * 32 + (tid - 128)];
    }
    __syncthreads();

    const int lane = tid & 31;
    const int w    = tid >> 5;
    const int i4w  = w << 2;               // first i4 group of this warp
    float* const post_r = out + Y_ELEMS + (size_t)r * INF;

#pragma unroll 2
    for (int t = 0; t < 8; ++t) {
        const int buf = t & 1;
        const int b0  = b0_base + (t << 5);

        // Front-batched, fully coalesced x loads (lanes = consecutive b).
        float4 xv[4];
#pragma unroll
        for (int g = 0; g < 4; ++g)
            xv[g] = g_xredT4[i4w + g][b0 + lane];

        float acc = 0.0f;
#pragma unroll
        for (int g = 0; g < 4; ++g) {
            const int  i4  = i4w + g;
            const int  i0  = i4 << 2;
            const int4 id4 = sf4[i4];      // 1 LDS.128 broadcast
            float4 pv;
            {
                float4 af = saf[i0 + 0];   // LDS.128 broadcast
                pv.x = fmaf(af.z, apply_fn(id4.x, fmaf(af.x, xv[g].x, af.y)), af.w);
            }
            {
                float4 af = saf[i0 + 1];
                pv.y = fmaf(af.z, apply_fn(id4.y, fmaf(af.x, xv[g].y, af.y)), af.w);
            }
            {
                float4 af = saf[i0 + 2];
                pv.z = fmaf(af.z, apply_fn(id4.z, fmaf(af.x, xv[g].z, af.y)), af.w);
            }
            {
                float4 af = saf[i0 + 3];
                pv.w = fmaf(af.z, apply_fn(id4.w, fmaf(af.x, xv[g].w, af.y)), af.w);
            }
            *reinterpret_cast<float4*>(&so[buf][lane][i0]) = pv;   // STS.128
            acc += (pv.x + pv.y) + (pv.z + pv.w);
        }
        spart[w][lane] = acc;
        __syncthreads();

        // Order generic-proxy STS before async-proxy bulk read, then ship the
        // tile: one 512B contiguous row per lane of warp 0.
        asm volatile("fence.proxy.async.shared::cta;" ::: "memory");
        if (tid < 32) {
            const int b = tid;
            unsigned int src = (unsigned int)__cvta_generic_to_shared(&so[buf][b][0]);
            float* dst = post_r + (size_t)(b0 + b) * POST_STRIDE;
            asm volatile("cp.async.bulk.global.shared::cta.bulk_group [%0], [%1], %2;"
                         :: "l"(dst), "r"(src), "r"(512u) : "memory");
            asm volatile("cp.async.bulk.commit_group;" ::: "memory");

            // y[b, r] = sum_i postacts[b, r, i]  (overlaps the in-flight copy)
            float s = spart[0][b];
#pragma unroll
            for (int ww = 1; ww < 8; ++ww) s += spart[ww][b];
            out[(size_t)(b0 + b) * OUTF + r] = s;

            // Keep <=1 copy outstanding: guarantees tile t-1's buffer is free
            // before tile t+1 overwrites it.
            asm volatile("cp.async.bulk.wait_group 1;" ::: "memory");
        }
        __syncthreads();
    }

    // Drain the final copy before the CTA (and its smem) retires.
    if (tid < 32)
        asm volatile("cp.async.bulk.wait_group 0;" ::: "memory");
}

// ---------------------------------------------------------------------------
extern "C" void kernel_launch(void* const* d_in, const int* in_sizes, int n_in,
                              void* d_out, int out_size) {
    const float*  x      = (const float*)d_in[0];
    const float4* affine = (const float4*)d_in[1];
    const float*  mask   = (const float*)d_in[2];
    const int*    fid    = (const int*)d_in[3];
    float*        out    = (float*)d_out;

    (void)in_sizes; (void)n_in; (void)out_size;

    xred_kernel<<<BATCH / 32, 256>>>(x, mask);
    kan_kernel<<<dim3(OUTF, BATCH / 256), 256>>>(affine, fid, out);
}

// round 11
// speedup vs baseline: 1.0678x; 1.0678x over previous
#include <cuda_runtime.h>
#include <cstdint>
#include <math.h>

#define BATCH 4096
#define INF   128
#define OUTF  128
#define POST_STRIDE (OUTF * INF)      // 16384 floats per batch row of postacts
#define Y_ELEMS (BATCH * OUTF)        // 524288
#define TILES_PER_BLOCK 4

// x_red stored TILE-TRANSPOSED for kan's access pattern:
// g_xredT4[i4][b] = float4( x_red[b][4*i4 .. 4*i4+3] ).  2 MB static scratch.
__device__ float4 g_xredT4[INF / 4][BATCH];

// ---------------------------------------------------------------------------
// Kernel 1: x_red[b, j] = sum_i x[b, i] * mask[j, i], written transposed.
// 128 blocks x 256 threads; 32 b-rows per block.
// ---------------------------------------------------------------------------
__global__ __launch_bounds__(256) void xred_kernel(const float* __restrict__ x,
                                                   const float* __restrict__ mask) {
    __shared__ float4 sx4[32][32];         // 32 b-rows x 128 floats

    const int tid = threadIdx.x;
    const int b0  = blockIdx.x * 32;
    const int j   = tid & 127;
    const int bh  = (tid >> 7) * 16;       // which 16-row half

    const float4* x4 = reinterpret_cast<const float4*>(x) + (size_t)b0 * 32;
#pragma unroll
    for (int k = 0; k < 4; ++k) {
        int idx = tid + k * 256;           // 0..1023
        sx4[idx >> 5][idx & 31] = x4[idx];
    }
    __syncthreads();

    const float4* m4 = reinterpret_cast<const float4*>(mask) + (size_t)j * 32;

    float acc[16];
#pragma unroll
    for (int b = 0; b < 16; ++b) acc[b] = 0.0f;

#pragma unroll 4
    for (int q = 0; q < 32; ++q) {
        float4 mv = __ldg(&m4[q]);
#pragma unroll
        for (int b = 0; b < 16; ++b) {
            float4 xv = sx4[bh + b][q];    // broadcast: conflict-free
            acc[b] += mv.x * xv.x + mv.y * xv.y + mv.z * xv.z + mv.w * xv.w;
        }
    }

    const int i4   = j >> 2;
    const int comp = j & 3;
#pragma unroll
    for (int b = 0; b < 16; ++b)
        reinterpret_cast<float*>(&g_xredT4[i4][b0 + bh + b])[comp] = acc[b];
}

// ---------------------------------------------------------------------------
// Activation body. `id` is warp-uniform at every call site -> single branch
// taken per warp. MUFU fast paths (abs err ~1e-6), atanf stays libm.
// ---------------------------------------------------------------------------
__device__ __forceinline__ float apply_fn(int id, float z) {
    switch (id) {
        case 0: return z;
        case 1: return z * z;
        case 2: return z * z * z;
        case 3: return __sinf(z);
        case 4: {                                   // tanh, saturates at +/-inf
            float e = __expf(2.0f * z);
            return 1.0f - 2.0f * __fdividef(1.0f, e + 1.0f);
        }
        case 5: return __fdividef(1.0f, 1.0f + __expf(-z));   // sigmoid
        case 6: return __expf(-z * z);
        case 7: return fabsf(z);
        case 8: return atanf(z);
        default: return __expf(z);                  // id == 9
    }
}

// ---------------------------------------------------------------------------
// Kernel 2: main KAN layer (R7 structure + 4-tile amortization, NO async copy).
// Grid: (r = 128, chunk = 32); block owns 4 consecutive 32-batch tiles at
// fixed r. saf/sf4 loaded once per block. Per tile: coalesced LDG.128 of
// pre-transposed x_red, uniform-branch compute (lanes = batch), STS.128 into
// stride-132 so[] (conflict-free), then all-warp LDS.128 + STG.128 (__stcs)
// epilogue -- fully parallel, no fences, 2 barriers/tile.
// ---------------------------------------------------------------------------
__global__ __launch_bounds__(256) void kan_kernel(const float4* __restrict__ affine4,
                                                  const int*   __restrict__ fids,
                                                  float*       __restrict__ out) {
    const int r       = blockIdx.x;
    const int b0_base = blockIdx.y << 7;   // 4 tiles * 32 batch

    __shared__ __align__(16) float so[32][132];
    __shared__ float4 saf[128];            // affine[r][i][0..3]
    __shared__ int4   sf4[32];             // fun_ids packed 4-wide
    __shared__ float  spart[8][32];

    const int tid = threadIdx.x;

    if (tid < 128) {
        saf[tid] = affine4[r * 128 + tid];
    } else if (tid < 160) {
        sf4[tid - 128] = reinterpret_cast<const int4*>(fids)[r * 32 + (tid - 128)];
    }
    __syncthreads();

    const int lane = tid & 31;
    const int w    = tid >> 5;
    const int i4w  = w << 2;               // first i4 group of this warp
    float* const post_r = out + Y_ELEMS + (size_t)r * INF;

#pragma unroll 1
    for (int t = 0; t < TILES_PER_BLOCK; ++t) {
        const int b0 = b0_base + (t << 5);

        // Front-batched, fully coalesced x loads (lanes = consecutive b).
        float4 xv[4];
#pragma unroll
        for (int g = 0; g < 4; ++g)
            xv[g] = g_xredT4[i4w + g][b0 + lane];

        float acc = 0.0f;
#pragma unroll
        for (int g = 0; g < 4; ++g) {
            const int  i4  = i4w + g;
            const int  i0  = i4 << 2;
            const int4 id4 = sf4[i4];      // 1 LDS.128 broadcast
            float4 pv;
            {
                float4 af = saf[i0 + 0];   // LDS.128 broadcast
                pv.x = fmaf(af.z, apply_fn(id4.x, fmaf(af.x, xv[g].x, af.y)), af.w);
            }
            {
                float4 af = saf[i0 + 1];
                pv.y = fmaf(af.z, apply_fn(id4.y, fmaf(af.x, xv[g].y, af.y)), af.w);
            }
            {
                float4 af = saf[i0 + 2];
                pv.z = fmaf(af.z, apply_fn(id4.z, fmaf(af.x, xv[g].z, af.y)), af.w);
            }
            {
                float4 af = saf[i0 + 3];
                pv.w = fmaf(af.z, apply_fn(id4.w, fmaf(af.x, xv[g].w, af.y)), af.w);
            }
            *reinterpret_cast<float4*>(&so[lane][i0]) = pv;    // STS.128
            acc += (pv.x + pv.y) + (pv.z + pv.w);
        }
        spart[w][lane] = acc;
        __syncthreads();

        // Epilogue: all 8 warps stream the 32x128 tile out, LDS.128 + STG.128.
#pragma unroll
        for (int k = 0; k < 4; ++k) {
            int idx = tid + k * 256;
            int b = idx >> 5, i4 = idx & 31;
            float4 v = *reinterpret_cast<const float4*>(&so[b][i4 * 4]);
            __stcs(reinterpret_cast<float4*>(&post_r[(size_t)(b0 + b) * POST_STRIDE + i4 * 4]), v);
        }

        // y[b, r] = sum_i postacts[b, r, i]
        if (tid < 32) {
            float s = spart[0][tid];
#pragma unroll
            for (int ww = 1; ww < 8; ++ww) s += spart[ww][tid];
            out[(size_t)(b0 + tid) * OUTF + r] = s;
        }
        __syncthreads();                   // so[] free for next tile
    }
}

// ---------------------------------------------------------------------------
extern "C" void kernel_launch(void* const* d_in, const int* in_sizes, int n_in,
                              void* d_out, int out_size) {
    const float*  x      = (const float*)d_in[0];
    const float4* affine = (const float4*)d_in[1];
    const float*  mask   = (const float*)d_in[2];
    const int*    fid    = (const int*)d_in[3];
    float*        out    = (float*)d_out;

    (void)in_sizes; (void)n_in; (void)out_size;

    xred_kernel<<<BATCH / 32, 256>>>(x, mask);
    kan_kernel<<<dim3(OUTF, BATCH / (32 * TILES_PER_BLOCK)), 256>>>(affine, fid, out);
}

// round 13
// speedup vs baseline: 1.3133x; 1.2299x over previous
#include <cuda_runtime.h>
#include <cstdint>
#include <math.h>

#define BATCH 4096
#define INF   128
#define OUTF  128
#define POST_STRIDE (OUTF * INF)      // 16384 floats per batch row of postacts
#define Y_ELEMS (BATCH * OUTF)        // 524288

// x_red stored TILE-TRANSPOSED for kan's access pattern:
// g_xredT4[i4][b] = float4( x_red[b][4*i4 .. 4*i4+3] ).  2 MB static scratch.
__device__ float4 g_xredT4[INF / 4][BATCH];

// ---------------------------------------------------------------------------
// Kernel 1 (R11 version -- best measured): x_red = x @ mask^T, transposed out.
// 128 blocks x 256 threads; 32 b-rows per block.
// ---------------------------------------------------------------------------
__global__ __launch_bounds__(256) void xred_kernel(const float* __restrict__ x,
                                                   const float* __restrict__ mask) {
    __shared__ float4 sx4[32][32];         // 32 b-rows x 128 floats

    const int tid = threadIdx.x;
    const int b0  = blockIdx.x * 32;
    const int j   = tid & 127;
    const int bh  = (tid >> 7) * 16;       // which 16-row half

    const float4* x4 = reinterpret_cast<const float4*>(x) + (size_t)b0 * 32;
#pragma unroll
    for (int k = 0; k < 4; ++k) {
        int idx = tid + k * 256;           // 0..1023
        sx4[idx >> 5][idx & 31] = x4[idx];
    }
    __syncthreads();

    const float4* m4 = reinterpret_cast<const float4*>(mask) + (size_t)j * 32;

    float acc[16];
#pragma unroll
    for (int b = 0; b < 16; ++b) acc[b] = 0.0f;

#pragma unroll 4
    for (int q = 0; q < 32; ++q) {
        float4 mv = __ldg(&m4[q]);
#pragma unroll
        for (int b = 0; b < 16; ++b) {
            float4 xv = sx4[bh + b][q];    // broadcast: conflict-free
            acc[b] += mv.x * xv.x + mv.y * xv.y + mv.z * xv.z + mv.w * xv.w;
        }
    }

    const int i4   = j >> 2;
    const int comp = j & 3;
#pragma unroll
    for (int b = 0; b < 16; ++b)
        reinterpret_cast<float*>(&g_xredT4[i4][b0 + bh + b])[comp] = acc[b];
}

// ---------------------------------------------------------------------------
// Activation body. `id` is warp-uniform at every call site -> single branch
// taken per warp. MUFU fast paths (abs err ~1e-6), atanf stays libm.
// ---------------------------------------------------------------------------
__device__ __forceinline__ float apply_fn(int id, float z) {
    switch (id) {
        case 0: return z;
        case 1: return z * z;
        case 2: return z * z * z;
        case 3: return __sinf(z);
        case 4: {                                   // tanh, saturates at +/-inf
            float e = __expf(2.0f * z);
            return 1.0f - 2.0f * __fdividef(1.0f, e + 1.0f);
        }
        case 5: return __fdividef(1.0f, 1.0f + __expf(-z));   // sigmoid
        case 6: return __expf(-z * z);
        case 7: return fabsf(z);
        case 8: return atanf(z);
        default: return __expf(z);                  // id == 9
    }
}

// ---------------------------------------------------------------------------
// Kernel 2 (R7 version -- best measured, 80.7us): main KAN layer.
// Grid: (r = 128, b_tile = 128), 256 threads. ONE 32x128 tile per block.
// Warp w owns i in [w*16, w*16+16); lanes map to batch -> fun_id warp-uniform.
// x_red via coalesced LDG.128 from pre-transposed g_xredT4 (no input staging).
// postacts tile staged in so[] (stride 132, conflict-free both phases), then
// all-warp LDS.128 + STG.128 (__stcs streaming) epilogue. y via smem partials.
// ---------------------------------------------------------------------------
__global__ __launch_bounds__(256) void kan_kernel(const float4* __restrict__ affine4,
                                                  const int*   __restrict__ fids,
                                                  float*       __restrict__ out) {
    const int r  = blockIdx.x;
    const int b0 = blockIdx.y << 5;        // 32-batch tile

    __shared__ __align__(16) float so[32][132];
    __shared__ float4 saf[128];            // affine[r][i][0..3]
    __shared__ int4   sf4[32];             // fun_ids packed 4-wide
    __shared__ float  spart[8][32];

    const int tid = threadIdx.x;

    if (tid < 128) {
        saf[tid] = affine4[r * 128 + tid];
    } else if (tid < 160) {
        sf4[tid - 128] = reinterpret_cast<const int4*>(fids)[r * 32 + (tid - 128)];
    }
    __syncthreads();

    const int lane = tid & 31;
    const int w    = tid >> 5;
    const int i4w  = w << 2;               // first i4 group of this warp

    // Front-batched, fully coalesced x loads (lanes = consecutive b).
    float4 xv[4];
#pragma unroll
    for (int g = 0; g < 4; ++g)
        xv[g] = g_xredT4[i4w + g][b0 + lane];

    float acc = 0.0f;
#pragma unroll
    for (int g = 0; g < 4; ++g) {
        const int  i4  = i4w + g;
        const int  i0  = i4 << 2;
        const int4 id4 = sf4[i4];          // 1 LDS.128 broadcast
        float4 pv;
        {
            float4 af = saf[i0 + 0];       // LDS.128 broadcast
            pv.x = fmaf(af.z, apply_fn(id4.x, fmaf(af.x, xv[g].x, af.y)), af.w);
        }
        {
            float4 af = saf[i0 + 1];
            pv.y = fmaf(af.z, apply_fn(id4.y, fmaf(af.x, xv[g].y, af.y)), af.w);
        }
        {
            float4 af = saf[i0 + 2];
            pv.z = fmaf(af.z, apply_fn(id4.z, fmaf(af.x, xv[g].z, af.y)), af.w);
        }
        {
            float4 af = saf[i0 + 3];
            pv.w = fmaf(af.z, apply_fn(id4.w, fmaf(af.x, xv[g].w, af.y)), af.w);
        }
        *reinterpret_cast<float4*>(&so[lane][i0]) = pv;    // STS.128, conflict-free
        acc += (pv.x + pv.y) + (pv.z + pv.w);
    }
    spart[w][lane] = acc;
    __syncthreads();

    // Epilogue: all 8 warps stream the 32x128 tile out, LDS.128 + STG.128.
    float* post = out + Y_ELEMS + (size_t)b0 * POST_STRIDE + (size_t)r * INF;
#pragma unroll
    for (int k = 0; k < 4; ++k) {
        int idx = tid + k * 256;
        int b = idx >> 5, i4 = idx & 31;
        float4 v = *reinterpret_cast<const float4*>(&so[b][i4 * 4]);
        __stcs(reinterpret_cast<float4*>(&post[(size_t)b * POST_STRIDE + i4 * 4]), v);
    }

    // y[b, r] = sum_i postacts[b, r, i]
    if (tid < 32) {
        float s = spart[0][tid];
#pragma unroll
        for (int ww = 1; ww < 8; ++ww) s += spart[ww][tid];
        out[(size_t)(b0 + tid) * OUTF + r] = s;
    }
}

// ---------------------------------------------------------------------------
extern "C" void kernel_launch(void* const* d_in, const int* in_sizes, int n_in,
                              void* d_out, int out_size) {
    const float*  x      = (const float*)d_in[0];
    const float4* affine = (const float4*)d_in[1];
    const float*  mask   = (const float*)d_in[2];
    const int*    fid    = (const int*)d_in[3];
    float*        out    = (float*)d_out;

    (void)in_sizes; (void)n_in; (void)out_size;

    xred_kernel<<<BATCH / 32, 256>>>(x, mask);
    kan_kernel<<<dim3(OUTF, BATCH / 32), 256>>>(affine, fid, out);
}

// round 16
// speedup vs baseline: 1.3564x; 1.0328x over previous
#include <cuda_runtime.h>
#include <cstdint>
#include <math.h>

#define BATCH 4096
#define INF   128
#define OUTF  128
#define POST_STRIDE (OUTF * INF)      // 16384 floats per batch row of postacts
#define Y_ELEMS (BATCH * OUTF)        // 524288

// x_red stored TILE-TRANSPOSED for kan's access pattern:
// g_xredT4[i4][b] = float4( x_red[b][4*i4 .. 4*i4+3] ).  2 MB static scratch.
__device__ float4 g_xredT4[INF / 4][BATCH];

// ---------------------------------------------------------------------------
// Kernel 1 v3: x_red = x @ mask^T, transposed out.
// 256 blocks x 128 threads; block = 16 b x 128 j. Thread = 2 j (j, j+64) x 8 b.
// Mask chunks staged in smem via COALESCED loads (fixes the 32-wf/LDG lane
// scatter of the previous version); smk rows padded to 36 floats so LDS.128
// at lane-stride 36 is phase-conflict-free. x tile broadcast from smem.
// ---------------------------------------------------------------------------
__global__ __launch_bounds__(128) void xred_kernel(const float* __restrict__ x,
                                                   const float* __restrict__ mask) {
    __shared__ float4 sx4[16][32];         // 16 b-rows x 128 floats (8 KB)
    __shared__ float  smk[128][36];        // mask chunk: 128 j x 32 i, padded (18 KB)

    const int tid = threadIdx.x;
    const int b0  = blockIdx.x * 16;
    const int jlo = tid & 63;              // this thread's low j (also handles jlo+64)
    const int bg  = (tid >> 6) * 8;        // base of this thread's 8 b rows

    // Load x tile, coalesced: 512 float4s by 128 threads.
    const float4* x4 = reinterpret_cast<const float4*>(x) + (size_t)b0 * 32;
#pragma unroll
    for (int k = 0; k < 4; ++k) {
        int idx = tid + k * 128;           // 0..511
        sx4[idx >> 5][idx & 31] = x4[idx];
    }

    const float4* m4 = reinterpret_cast<const float4*>(mask);

    float acc[2][8];
#pragma unroll
    for (int jj = 0; jj < 2; ++jj)
#pragma unroll
        for (int b = 0; b < 8; ++b) acc[jj][b] = 0.0f;

    for (int c = 0; c < 4; ++c) {          // 4 chunks of 32 i
        __syncthreads();                   // smk reuse + (c==0) x-tile visibility
        // Coalesced mask chunk load: 128 rows x 8 float4s.
#pragma unroll
        for (int k = 0; k < 8; ++k) {
            int idx = tid + k * 128;       // 0..1023
            int row = idx >> 3, c4 = idx & 7;
            float4 v = __ldg(&m4[row * 32 + c * 8 + c4]);
            *reinterpret_cast<float4*>(&smk[row][c4 * 4]) = v;
        }
        __syncthreads();

#pragma unroll
        for (int q = 0; q < 8; ++q) {
            float4 m0 = *reinterpret_cast<const float4*>(&smk[jlo][q * 4]);
            float4 m1 = *reinterpret_cast<const float4*>(&smk[jlo + 64][q * 4]);
#pragma unroll
            for (int b = 0; b < 8; ++b) {
                float4 xv = sx4[bg + b][c * 8 + q];    // broadcast: conflict-free
                acc[0][b] += m0.x * xv.x + m0.y * xv.y + m0.z * xv.z + m0.w * xv.w;
                acc[1][b] += m1.x * xv.x + m1.y * xv.y + m1.z * xv.z + m1.w * xv.w;
            }
        }
    }

#pragma unroll
    for (int jj = 0; jj < 2; ++jj) {
        const int j    = jlo + jj * 64;
        const int i4   = j >> 2;
        const int comp = j & 3;
#pragma unroll
        for (int b = 0; b < 8; ++b)
            reinterpret_cast<float*>(&g_xredT4[i4][b0 + bg + b])[comp] = acc[jj][b];
    }
}

// ---------------------------------------------------------------------------
// Activation body. `id` is warp-uniform at every call site -> single branch
// taken per warp. MUFU fast paths (abs err ~1e-6), atanf stays libm.
// ---------------------------------------------------------------------------
__device__ __forceinline__ float apply_fn(int id, float z) {
    switch (id) {
        case 0: return z;
        case 1: return z * z;
        case 2: return z * z * z;
        case 3: return __sinf(z);
        case 4: {                                   // tanh, saturates at +/-inf
            float e = __expf(2.0f * z);
            return 1.0f - 2.0f * __fdividef(1.0f, e + 1.0f);
        }
        case 5: return __fdividef(1.0f, 1.0f + __expf(-z));   // sigmoid
        case 6: return __expf(-z * z);
        case 7: return fabsf(z);
        case 8: return atanf(z);
        default: return __expf(z);                  // id == 9
    }
}

// ---------------------------------------------------------------------------
// Kernel 2 (UNCHANGED -- twice-reproduced 80.8us ridge): main KAN layer.
// Grid: (r = 128, b_tile = 128), 256 threads. ONE 32x128 tile per block.
// Warp w owns i in [w*16, w*16+16); lanes map to batch -> fun_id warp-uniform.
// x_red via coalesced LDG.128 from pre-transposed g_xredT4 (no input staging).
// postacts tile staged in so[] (stride 132, conflict-free both phases), then
// all-warp LDS.128 + STG.128 (__stcs streaming) epilogue. y via smem partials.
// ---------------------------------------------------------------------------
__global__ __launch_bounds__(256) void kan_kernel(const float4* __restrict__ affine4,
                                                  const int*   __restrict__ fids,
                                                  float*       __restrict__ out) {
    const int r  = blockIdx.x;
    const int b0 = blockIdx.y << 5;        // 32-batch tile

    __shared__ __align__(16) float so[32][132];
    __shared__ float4 saf[128];            // affine[r][i][0..3]
    __shared__ int4   sf4[32];             // fun_ids packed 4-wide
    __shared__ float  spart[8][32];

    const int tid = threadIdx.x;

    if (tid < 128) {
        saf[tid] = affine4[r * 128 + tid];
    } else if (tid < 160) {
        sf4[tid - 128] = reinterpret_cast<const int4*>(fids)[r * 32 + (tid - 128)];
    }
    __syncthreads();

    const int lane = tid & 31;
    const int w    = tid >> 5;
    const int i4w  = w << 2;               // first i4 group of this warp

    // Front-batched, fully coalesced x loads (lanes = consecutive b).
    float4 xv[4];
#pragma unroll
    for (int g = 0; g < 4; ++g)
        xv[g] = g_xredT4[i4w + g][b0 + lane];

    float acc = 0.0f;
#pragma unroll
    for (int g = 0; g < 4; ++g) {
        const int  i4  = i4w + g;
        const int  i0  = i4 << 2;
        const int4 id4 = sf4[i4];          // 1 LDS.128 broadcast
        float4 pv;
        {
            float4 af = saf[i0 + 0];       // LDS.128 broadcast
            pv.x = fmaf(af.z, apply_fn(id4.x, fmaf(af.x, xv[g].x, af.y)), af.w);
        }
        {
            float4 af = saf[i0 + 1];
            pv.y = fmaf(af.z, apply_fn(id4.y, fmaf(af.x, xv[g].y, af.y)), af.w);
        }
        {
            float4 af = saf[i0 + 2];
            pv.z = fmaf(af.z, apply_fn(id4.z, fmaf(af.x, xv[g].z, af.y)), af.w);
        }
        {
            float4 af = saf[i0 + 3];
            pv.w = fmaf(af.z, apply_fn(id4.w, fmaf(af.x, xv[g].w, af.y)), af.w);
        }
        *reinterpret_cast<float4*>(&so[lane][i0]) = pv;    // STS.128, conflict-free
        acc += (pv.x + pv.y) + (pv.z + pv.w);
    }
    spart[w][lane] = acc;
    __syncthreads();

    // Epilogue: all 8 warps stream the 32x128 tile out, LDS.128 + STG.128.
    float* post = out + Y_ELEMS + (size_t)b0 * POST_STRIDE + (size_t)r * INF;
#pragma unroll
    for (int k = 0; k < 4; ++k) {
        int idx = tid + k * 256;
        int b = idx >> 5, i4 = idx & 31;
        float4 v = *reinterpret_cast<const float4*>(&so[b][i4 * 4]);
        __stcs(reinterpret_cast<float4*>(&post[(size_t)b * POST_STRIDE + i4 * 4]), v);
    }

    // y[b, r] = sum_i postacts[b, r, i]
    if (tid < 32) {
        float s = spart[0][tid];
#pragma unroll
        for (int ww = 1; ww < 8; ++ww) s += spart[ww][tid];
        out[(size_t)(b0 + tid) * OUTF + r] = s;
    }
}

// ---------------------------------------------------------------------------
extern "C" void kernel_launch(void* const* d_in, const int* in_sizes, int n_in,
                              void* d_out, int out_size) {
    const float*  x      = (const float*)d_in[0];
    const float4* affine = (const float4*)d_in[1];
    const float*  mask   = (const float*)d_in[2];
    const int*    fid    = (const int*)d_in[3];
    float*        out    = (float*)d_out;

    (void)in_sizes; (void)n_in; (void)out_size;

    xred_kernel<<<BATCH / 16, 128>>>(x, mask);
    kan_kernel<<<dim3(OUTF, BATCH / 32), 256>>>(affine, fid, out);
}

// round 17
// speedup vs baseline: 1.6138x; 1.1898x over previous
#include <cuda_runtime.h>
#include <cstdint>
#include <math.h>

#define BATCH 4096
#define INF   128
#define OUTF  128
#define POST_STRIDE (OUTF * INF)      // 16384 floats per batch row of postacts
#define Y_ELEMS (BATCH * OUTF)        // 524288

// x_red stored TILE-TRANSPOSED for kan's access pattern:
// g_xredT4[i4][b] = float4( x_red[b][4*i4 .. 4*i4+3] ).  2 MB static scratch.
__device__ float4 g_xredT4[INF / 4][BATCH];

// ---------------------------------------------------------------------------
// Kernel 1 (unchanged from R16): x_red = x @ mask^T, transposed out.
// 256 blocks x 128 threads; block = 16 b x 128 j. Coalesced mask staging.
// ---------------------------------------------------------------------------
__global__ __launch_bounds__(128) void xred_kernel(const float* __restrict__ x,
                                                   const float* __restrict__ mask) {
    __shared__ float4 sx4[16][32];         // 16 b-rows x 128 floats
    __shared__ float  smk[128][36];        // mask chunk, padded rows

    const int tid = threadIdx.x;
    const int b0  = blockIdx.x * 16;
    const int jlo = tid & 63;
    const int bg  = (tid >> 6) * 8;

    const float4* x4 = reinterpret_cast<const float4*>(x) + (size_t)b0 * 32;
#pragma unroll
    for (int k = 0; k < 4; ++k) {
        int idx = tid + k * 128;
        sx4[idx >> 5][idx & 31] = x4[idx];
    }

    const float4* m4 = reinterpret_cast<const float4*>(mask);

    float acc[2][8];
#pragma unroll
    for (int jj = 0; jj < 2; ++jj)
#pragma unroll
        for (int b = 0; b < 8; ++b) acc[jj][b] = 0.0f;

    for (int c = 0; c < 4; ++c) {
        __syncthreads();
#pragma unroll
        for (int k = 0; k < 8; ++k) {
            int idx = tid + k * 128;
            int row = idx >> 3, c4 = idx & 7;
            float4 v = __ldg(&m4[row * 32 + c * 8 + c4]);
            *reinterpret_cast<float4*>(&smk[row][c4 * 4]) = v;
        }
        __syncthreads();

#pragma unroll
        for (int q = 0; q < 8; ++q) {
            float4 m0 = *reinterpret_cast<const float4*>(&smk[jlo][q * 4]);
            float4 m1 = *reinterpret_cast<const float4*>(&smk[jlo + 64][q * 4]);
#pragma unroll
            for (int b = 0; b < 8; ++b) {
                float4 xv = sx4[bg + b][c * 8 + q];
                acc[0][b] += m0.x * xv.x + m0.y * xv.y + m0.z * xv.z + m0.w * xv.w;
                acc[1][b] += m1.x * xv.x + m1.y * xv.y + m1.z * xv.z + m1.w * xv.w;
            }
        }
    }

#pragma unroll
    for (int jj = 0; jj < 2; ++jj) {
        const int j    = jlo + jj * 64;
        const int i4   = j >> 2;
        const int comp = j & 3;
#pragma unroll
        for (int b = 0; b < 8; ++b)
            reinterpret_cast<float*>(&g_xredT4[i4][b0 + bg + b])[comp] = acc[jj][b];
    }
}

// ---------------------------------------------------------------------------
// Paired activation: ONE warp-uniform switch evaluates the chosen body for
// TWO elements (amortizes branch dispatch across the 2 b's per thread).
// ---------------------------------------------------------------------------
__device__ __forceinline__ void apply_fn2(int id, float za, float zb,
                                          float& fa, float& fb) {
    switch (id) {
        case 0: fa = za; fb = zb; break;
        case 1: fa = za * za; fb = zb * zb; break;
        case 2: fa = za * za * za; fb = zb * zb * zb; break;
        case 3: fa = __sinf(za); fb = __sinf(zb); break;
        case 4: {                                   // tanh, saturates at +/-inf
            float ea = __expf(2.0f * za), eb = __expf(2.0f * zb);
            fa = 1.0f - 2.0f * __fdividef(1.0f, ea + 1.0f);
            fb = 1.0f - 2.0f * __fdividef(1.0f, eb + 1.0f);
            break;
        }
        case 5:
            fa = __fdividef(1.0f, 1.0f + __expf(-za));
            fb = __fdividef(1.0f, 1.0f + __expf(-zb));
            break;
        case 6: fa = __expf(-za * za); fb = __expf(-zb * zb); break;
        case 7: fa = fabsf(za); fb = fabsf(zb); break;
        case 8: fa = atanf(za); fb = atanf(zb); break;
        default: fa = __expf(za); fb = __expf(zb); break;    // id == 9
    }
}

// ---------------------------------------------------------------------------
// Kernel 2: main KAN layer, 64-batch tile, 2 b per thread.
// Grid: (r = 128, b_tile = 64), 256 threads, SAME 2-barrier structure as the
// 80.8us ridge. Warp w owns i in [w*16,+16); thread handles b = lane and
// lane+32 -> affine/fun_id broadcasts and switch dispatch amortized over 2 b.
// so[] is 64x128 float with XOR swizzle (i4 ^ (b&7)): conflict-free STS
// (8 distinct quads per phase) and epilogue LDS (b const, i4 = lane ^ c).
// Epilogue: all warps LDS.128 + STG.128 (__stcs), fully coalesced.
// ---------------------------------------------------------------------------
__global__ __launch_bounds__(256, 6) void kan_kernel(const float4* __restrict__ affine4,
                                                     const int*   __restrict__ fids,
                                                     float*       __restrict__ out) {
    const int r  = blockIdx.x;
    const int b0 = blockIdx.y << 6;        // 64-batch tile

    __shared__ __align__(16) float4 so4[64 * 32];   // swizzled, 32 KB
    __shared__ float4 saf[128];            // affine[r][i][0..3]
    __shared__ int4   sf4[32];             // fun_ids packed 4-wide
    __shared__ float  spart[8][64];

    const int tid = threadIdx.x;

    if (tid < 128) {
        saf[tid] = affine4[r * 128 + tid];
    } else if (tid < 160) {
        sf4[tid - 128] = reinterpret_cast<const int4*>(fids)[r * 32 + (tid - 128)];
    }
    __syncthreads();

    const int lane = tid & 31;
    const int w    = tid >> 5;
    const int i4w  = w << 2;               // first i4 group of this warp
    const int sw   = lane & 7;             // swizzle key (same for lane and lane+32)

    float acc_a = 0.0f, acc_b = 0.0f;
#pragma unroll 1
    for (int g = 0; g < 4; ++g) {
        const int  i4 = i4w + g;
        const int  i0 = i4 << 2;
        // Coalesced LDG.128 pair: lanes = consecutive b.
        float4 xa = g_xredT4[i4][b0 + lane];
        float4 xb = g_xredT4[i4][b0 + 32 + lane];
        const int4 id4 = sf4[i4];          // LDS.128 broadcast (shared by 2 b)
        float4 pa, pb;
        {
            float4 af = saf[i0 + 0];       // LDS.128 broadcast (shared by 2 b)
            float fa, fb;
            apply_fn2(id4.x, fmaf(af.x, xa.x, af.y), fmaf(af.x, xb.x, af.y), fa, fb);
            pa.x = fmaf(af.z, fa, af.w);  pb.x = fmaf(af.z, fb, af.w);
        }
        {
            float4 af = saf[i0 + 1];
            float fa, fb;
            apply_fn2(id4.y, fmaf(af.x, xa.y, af.y), fmaf(af.x, xb.y, af.y), fa, fb);
            pa.y = fmaf(af.z, fa, af.w);  pb.y = fmaf(af.z, fb, af.w);
        }
        {
            float4 af = saf[i0 + 2];
            float fa, fb;
            apply_fn2(id4.z, fmaf(af.x, xa.z, af.y), fmaf(af.x, xb.z, af.y), fa, fb);
            pa.z = fmaf(af.z, fa, af.w);  pb.z = fmaf(af.z, fb, af.w);
        }
        {
            float4 af = saf[i0 + 3];
            float fa, fb;
            apply_fn2(id4.w, fmaf(af.x, xa.w, af.y), fmaf(af.x, xb.w, af.y), fa, fb);
            pa.w = fmaf(af.z, fa, af.w);  pb.w = fmaf(af.z, fb, af.w);
        }
        const int sw_i4 = i4 ^ sw;         // XOR swizzle
        so4[lane * 32 + sw_i4]        = pa;            // STS.128, conflict-free
        so4[(lane + 32) * 32 + sw_i4] = pb;
        acc_a += (pa.x + pa.y) + (pa.z + pa.w);
        acc_b += (pb.x + pb.y) + (pb.z + pb.w);
    }
    spart[w][lane]      = acc_a;
    spart[w][lane + 32] = acc_b;
    __syncthreads();

    // Epilogue: all 8 warps stream the 64x128 tile out. Warp reads b = const,
    // i4 = lane ^ (b&7): spans all banks, conflict-free; STG.128 coalesced.
    float* post = out + Y_ELEMS + (size_t)b0 * POST_STRIDE + (size_t)r * INF;
#pragma unroll
    for (int k = 0; k < 8; ++k) {
        int idx = tid + k * 256;           // 0..2047
        int b = idx >> 5, i4 = idx & 31;
        float4 v = so4[b * 32 + (i4 ^ (b & 7))];
        __stcs(reinterpret_cast<float4*>(&post[(size_t)b * POST_STRIDE + i4 * 4]), v);
    }

    // y[b, r] = sum_i postacts[b, r, i]
    if (tid < 64) {
        float s = spart[0][tid];
#pragma unroll
        for (int ww = 1; ww < 8; ++ww) s += spart[ww][tid];
        out[(size_t)(b0 + tid) * OUTF + r] = s;
    }
}

// ---------------------------------------------------------------------------
extern "C" void kernel_launch(void* const* d_in, const int* in_sizes, int n_in,
                              void* d_out, int out_size) {
    const float*  x      = (const float*)d_in[0];
    const float4* affine = (const float4*)d_in[1];
    const float*  mask   = (const float*)d_in[2];
    const int*    fid    = (const int*)d_in[3];
    float*        out    = (float*)d_out;

    (void)in_sizes; (void)n_in; (void)out_size;

    xred_kernel<<<BATCH / 16, 128>>>(x, mask);
    kan_kernel<<<dim3(OUTF, BATCH / 64), 256>>>(affine, fid, out);
}